// round 9
// baseline (speedup 1.0000x reference)
#include <cuda_runtime.h>
#include <cuda_bf16.h>
#include <math.h>
#include <stdint.h>

#define Bq   4
#define Nq   200000
#define Eq   128
#define IDXq 2048
#define TOT  (Bq * Nq)        // 800000 tokens
#define SEGS (Bq * IDXq)      // 8192 segments
#define OUTF (SEGS * Eq)      // 1048576 floats in `out` region
#define TM   128              // tokens per tile
#define TILES (TOT / TM)      // 6250 tiles
#define ROWB 272              // padded bf16 smem row stride (128 bf16 + 8 pad)
#define RAWS 528              // padded fp32 raw row stride bytes (132 floats)

// ---------------- device scratch (no cudaMalloc allowed) -------------------
__device__ float g_e[TOT];
__device__ float g_segsum[SEGS];
__device__ int   g_cnt[SEGS];
__device__ int   g_off[SEGS];     // segment start offsets (exclusive scan)
__device__ int   g_cur[SEGS];     // place cursors -> end offsets after place
__device__ int   g_ord[TOT];      // token ids sorted by segment
__device__ __nv_bfloat16 g_Whi[Eq * Eq];
__device__ __nv_bfloat16 g_Wlo[Eq * Eq];

// ---------------- helpers ---------------------------------------------------
__device__ __forceinline__ uint32_t smem_u32(const void* p) {
    uint32_t a;
    asm("{ .reg .u64 t; cvta.to.shared.u64 t, %1; cvt.u32.u64 %0, t; }" : "=r"(a) : "l"(p));
    return a;
}
__device__ __forceinline__ uint32_t pack_bf16x2(float a, float b) {
    uint32_t r;
    asm("cvt.rn.bf16x2.f32 %0, %1, %2;" : "=r"(r) : "f"(b), "f"(a));
    return r;
}
__device__ __forceinline__ void cp_async16(uint32_t saddr, const void* gaddr) {
    asm volatile("cp.async.cg.shared.global [%0], [%1], 16;" :: "r"(saddr), "l"(gaddr));
}
__device__ __forceinline__ void ldsm_x4(uint32_t addr, uint32_t& r0, uint32_t& r1,
                                        uint32_t& r2, uint32_t& r3) {
    asm volatile("ldmatrix.sync.aligned.m8n8.x4.shared.b16 {%0,%1,%2,%3}, [%4];"
                 : "=r"(r0), "=r"(r1), "=r"(r2), "=r"(r3) : "r"(addr));
}
__device__ __forceinline__ void mma_bf16(float* d, uint32_t a0, uint32_t a1, uint32_t a2,
                                         uint32_t a3, uint32_t b0, uint32_t b1) {
    asm volatile(
        "mma.sync.aligned.m16n8k16.row.col.f32.bf16.bf16.f32 "
        "{%0,%1,%2,%3}, {%4,%5,%6,%7}, {%8,%9}, {%0,%1,%2,%3};"
        : "+f"(d[0]), "+f"(d[1]), "+f"(d[2]), "+f"(d[3])
        : "r"(a0), "r"(a1), "r"(a2), "r"(a3), "r"(b0), "r"(b1));
}
// tanh(x) = 1 - 2/(exp(2x)+1), via ex2.approx + rcp.approx (~2^-21 max rel err)
__device__ __forceinline__ float fast_tanh(float x) {
    float e, r;
    asm("ex2.approx.f32 %0, %1;" : "=f"(e) : "f"(x * 2.8853900817779268f));
    asm("rcp.approx.f32 %0, %1;" : "=f"(r) : "f"(e + 1.0f));
    return fmaf(-2.0f, r, 1.0f);
}

// ---------------------------------------------------------------------------
__global__ void wprep_kernel(const float* __restrict__ W) {
    int i = blockIdx.x * blockDim.x + threadIdx.x; // 16384 exact
    float w = W[i];
    __nv_bfloat16 hi = __float2bfloat16_rn(w);
    g_Whi[i] = hi;
    g_Wlo[i] = __float2bfloat16_rn(w - __bfloat162float(hi));
}

// zero per-segment accumulators (idempotent across graph replays)
__global__ void zinit_kernel() {
    int i = blockIdx.x * blockDim.x + threadIdx.x;   // grid covers SEGS
    g_segsum[i] = 0.0f;
    g_cnt[i] = 0;
}

// ---------------------------------------------------------------------------
// Score pass: persistent HMMA bf16x3-split GEMM, cp.async pipelined.
// Emits e = mask ? exp(ctx.tanh(xW^T+b)/sqrt(E)) : 0 (no-max softmax),
// accumulates segsum and per-segment counts.
// ---------------------------------------------------------------------------
#define SM_B   0
#define SM_C   512
#define SM_P   1024                     // partial[128][2] floats
#define SM_WH  2048
#define SM_WL  (SM_WH + 128 * ROWB)
#define SM_XH  (SM_WL + 128 * ROWB)
#define SM_XL  (SM_XH + 128 * ROWB)
#define SM_RAW (SM_XL + 128 * ROWB)     // fp32 raw tile, stride 528B
#define SM_TOTAL (SM_RAW + 128 * RAWS)  // 208896

__global__ void __launch_bounds__(256, 1) score_kernel(
    const float* __restrict__ x, const float* __restrict__ bias,
    const float* __restrict__ ctx, const int* __restrict__ mask,
    const int* __restrict__ index)
{
    extern __shared__ char smem[];
    const uint32_t sb = smem_u32(smem);
    const int tid  = threadIdx.x;
    const int wid  = tid >> 5;
    const int lane = tid & 31;

    float* bS = reinterpret_cast<float*>(smem + SM_B);
    float* cS = reinterpret_cast<float*>(smem + SM_C);
    float* pS = reinterpret_cast<float*>(smem + SM_P);
    if (tid < 128) { bS[tid] = bias[tid]; cS[tid] = ctx[tid]; }

    // stage W hi/lo (row f, stride 272B). 256 thr, 128 rows.
    {
        const int r = tid >> 1;
        const int c0 = (tid & 1) * 64;
#pragma unroll
        for (int i = 0; i < 8; i++) {
            const int c = c0 + i * 8;
            *reinterpret_cast<uint4*>(smem + SM_WH + r * ROWB + c * 2) =
                *reinterpret_cast<const uint4*>(&g_Whi[r * Eq + c]);
            *reinterpret_cast<uint4*>(smem + SM_WL + r * ROWB + c * 2) =
                *reinterpret_cast<const uint4*>(&g_Wlo[r * Eq + c]);
        }
    }

    const int xr   = tid >> 1;
    const int half = (tid & 1) * 64;
    const uint32_t rawBase = sb + SM_RAW + (uint32_t)xr * RAWS + (uint32_t)half * 4;

    const int rowG = (wid >> 1) * 32;
    const int colG = (wid & 1) * 64;

    const uint32_t aColB = (lane >> 4) * 16;
    const uint32_t aAddr0H = sb + SM_XH + (uint32_t)(rowG + (lane & 15)) * ROWB + aColB;
    const uint32_t aAddr1H = aAddr0H + 16 * ROWB;
    const uint32_t dXL = (uint32_t)(SM_XL - SM_XH);
    const int rowB = (lane & 7) + ((lane & 16) >> 1);
    const uint32_t colB = (lane & 8) ? 16u : 0u;
    const uint32_t bBaseH = sb + SM_WH + (uint32_t)(colG + rowB) * ROWB + colB;
    const uint32_t dWL = (uint32_t)(SM_WL - SM_WH);

    // ---- prologue: cp.async tile0 -> raw, convert to hi/lo ----
    int tile = blockIdx.x;
    {
        const float* xrow = x + (size_t)(tile * TM + xr) * Eq + half;
#pragma unroll
        for (int i = 0; i < 16; i++) cp_async16(rawBase + i * 16, xrow + i * 4);
        asm volatile("cp.async.commit_group;" ::: "memory");
        asm volatile("cp.async.wait_group 0;" ::: "memory");
    }
    __syncthreads();
#pragma unroll
    for (int i = 0; i < 8; i++) {
        float4 f0 = *reinterpret_cast<const float4*>(smem + (rawBase - sb) + i * 32);
        float4 f1 = *reinterpret_cast<const float4*>(smem + (rawBase - sb) + i * 32 + 16);
        float fv[8] = {f0.x, f0.y, f0.z, f0.w, f1.x, f1.y, f1.z, f1.w};
        float hv[8], lv[8];
#pragma unroll
        for (int j = 0; j < 8; j++) {
            hv[j] = __bfloat162float(__float2bfloat16_rn(fv[j]));
            lv[j] = fv[j] - hv[j];
        }
        uint4 uh, ul;
        uh.x = pack_bf16x2(hv[0], hv[1]); uh.y = pack_bf16x2(hv[2], hv[3]);
        uh.z = pack_bf16x2(hv[4], hv[5]); uh.w = pack_bf16x2(hv[6], hv[7]);
        ul.x = pack_bf16x2(lv[0], lv[1]); ul.y = pack_bf16x2(lv[2], lv[3]);
        ul.z = pack_bf16x2(lv[4], lv[5]); ul.w = pack_bf16x2(lv[6], lv[7]);
        const int c = half + i * 8;
        *reinterpret_cast<uint4*>(smem + SM_XH + xr * ROWB + c * 2) = uh;
        *reinterpret_cast<uint4*>(smem + SM_XL + xr * ROWB + c * 2) = ul;
    }
    __syncthreads();

    while (tile < TILES) {
        const int tbase = tile * TM;
        const int next  = tile + gridDim.x;

        // ---- issue cp.async for next tile ----
        if (next < TILES) {
            const float* xrow = x + (size_t)(next * TM + xr) * Eq + half;
#pragma unroll
            for (int i = 0; i < 16; i++) cp_async16(rawBase + i * 16, xrow + i * 4);
            asm volatile("cp.async.commit_group;" ::: "memory");
        }

        // ---- MMA mainloop: d = xh*Wh + xh*Wl + xl*Wh ----
        float d[2][8][4];
#pragma unroll
        for (int mb = 0; mb < 2; mb++)
#pragma unroll
            for (int nb = 0; nb < 8; nb++)
#pragma unroll
                for (int j = 0; j < 4; j++) d[mb][nb][j] = 0.0f;

#pragma unroll
        for (int k = 0; k < 8; k++) {
            const uint32_t ko = (uint32_t)k * 32;
            uint32_t ah[2][4], al[2][4];
            ldsm_x4(aAddr0H + ko,       ah[0][0], ah[0][1], ah[0][2], ah[0][3]);
            ldsm_x4(aAddr0H + dXL + ko, al[0][0], al[0][1], al[0][2], al[0][3]);
            ldsm_x4(aAddr1H + ko,       ah[1][0], ah[1][1], ah[1][2], ah[1][3]);
            ldsm_x4(aAddr1H + dXL + ko, al[1][0], al[1][1], al[1][2], al[1][3]);
#pragma unroll
            for (int nb = 0; nb < 4; nb++) {
                uint32_t bh0, bh1, bh2, bh3, bl0, bl1, bl2, bl3;
                const uint32_t boff = (uint32_t)nb * (16 * ROWB) + ko;
                ldsm_x4(bBaseH + boff,       bh0, bh1, bh2, bh3);
                ldsm_x4(bBaseH + dWL + boff, bl0, bl1, bl2, bl3);
#pragma unroll
                for (int mb = 0; mb < 2; mb++) {
                    mma_bf16(d[mb][nb * 2],     ah[mb][0], ah[mb][1], ah[mb][2], ah[mb][3], bh0, bh1);
                    mma_bf16(d[mb][nb * 2],     ah[mb][0], ah[mb][1], ah[mb][2], ah[mb][3], bl0, bl1);
                    mma_bf16(d[mb][nb * 2],     al[mb][0], al[mb][1], al[mb][2], al[mb][3], bh0, bh1);
                    mma_bf16(d[mb][nb * 2 + 1], ah[mb][0], ah[mb][1], ah[mb][2], ah[mb][3], bh2, bh3);
                    mma_bf16(d[mb][nb * 2 + 1], ah[mb][0], ah[mb][1], ah[mb][2], ah[mb][3], bl2, bl3);
                    mma_bf16(d[mb][nb * 2 + 1], al[mb][0], al[mb][1], al[mb][2], al[mb][3], bh2, bh3);
                }
            }
        }

        // ---- epilogue: per-warp partial of ctx . tanh(z + b) over 64 cols ----
#pragma unroll
        for (int mb = 0; mb < 2; mb++) {
            float p0 = 0.0f, p1 = 0.0f;
#pragma unroll
            for (int nb = 0; nb < 8; nb++) {
                const int n0 = colG + nb * 8 + (lane & 3) * 2;
                const float2 bb = *reinterpret_cast<const float2*>(&bS[n0]);
                const float2 cc = *reinterpret_cast<const float2*>(&cS[n0]);
                p0 = fmaf(fast_tanh(d[mb][nb][0] + bb.x), cc.x, p0);
                p0 = fmaf(fast_tanh(d[mb][nb][1] + bb.y), cc.y, p0);
                p1 = fmaf(fast_tanh(d[mb][nb][2] + bb.x), cc.x, p1);
                p1 = fmaf(fast_tanh(d[mb][nb][3] + bb.y), cc.y, p1);
            }
            p0 += __shfl_xor_sync(0xffffffffu, p0, 1);
            p0 += __shfl_xor_sync(0xffffffffu, p0, 2);
            p1 += __shfl_xor_sync(0xffffffffu, p1, 1);
            p1 += __shfl_xor_sync(0xffffffffu, p1, 2);
            if ((lane & 3) == 0) {
                const int r = rowG + mb * 16 + (lane >> 2);
                pS[r * 2 + (wid & 1)]       = p0;
                pS[(r + 8) * 2 + (wid & 1)] = p1;
            }
        }
        asm volatile("cp.async.wait_group 0;" ::: "memory");
        __syncthreads();   // partials visible; ldsm done; raw tile landed

        // ---- finalize: e = mask ? exp(score) : 0; segsum += e; cnt += 1 ----
        if (tid < 128) {
            const int tok = tbase + tid;
            const float s = (pS[tid * 2] + pS[tid * 2 + 1]) * 0.08838834764831845f;
            const float e = (mask[tok] == 0) ? 0.0f : __expf(s);
            g_e[tok] = e;
            const int seg = (tok / Nq) * IDXq + index[tok];
            atomicAdd(&g_segsum[seg], e);
            atomicAdd(&g_cnt[seg], 1);
        }

        // ---- convert raw -> hi/lo for next tile ----
        if (next < TILES) {
#pragma unroll
            for (int i = 0; i < 8; i++) {
                float4 f0 = *reinterpret_cast<const float4*>(smem + (rawBase - sb) + i * 32);
                float4 f1 = *reinterpret_cast<const float4*>(smem + (rawBase - sb) + i * 32 + 16);
                float fv[8] = {f0.x, f0.y, f0.z, f0.w, f1.x, f1.y, f1.z, f1.w};
                float hv[8], lv[8];
#pragma unroll
                for (int j = 0; j < 8; j++) {
                    hv[j] = __bfloat162float(__float2bfloat16_rn(fv[j]));
                    lv[j] = fv[j] - hv[j];
                }
                uint4 uh, ul;
                uh.x = pack_bf16x2(hv[0], hv[1]); uh.y = pack_bf16x2(hv[2], hv[3]);
                uh.z = pack_bf16x2(hv[4], hv[5]); uh.w = pack_bf16x2(hv[6], hv[7]);
                ul.x = pack_bf16x2(lv[0], lv[1]); ul.y = pack_bf16x2(lv[2], lv[3]);
                ul.z = pack_bf16x2(lv[4], lv[5]); ul.w = pack_bf16x2(lv[6], lv[7]);
                const int c = half + i * 8;
                *reinterpret_cast<uint4*>(smem + SM_XH + xr * ROWB + c * 2) = uh;
                *reinterpret_cast<uint4*>(smem + SM_XL + xr * ROWB + c * 2) = ul;
            }
        }
        __syncthreads();
        tile = next;
    }
}

// ---------------------------------------------------------------------------
// Scan: exclusive prefix sum of g_cnt -> g_off (and cursor copy g_cur).
// Single block, 1024 threads x 8 elements.
// ---------------------------------------------------------------------------
__global__ void __launch_bounds__(1024) scan_kernel() {
    __shared__ int sm[1024];
    const int tid = threadIdx.x;
    int4 c0 = reinterpret_cast<const int4*>(g_cnt)[tid * 2];
    int4 c1 = reinterpret_cast<const int4*>(g_cnt)[tid * 2 + 1];
    int v[8] = {c0.x, c0.y, c0.z, c0.w, c1.x, c1.y, c1.z, c1.w};
    int pre[8];
    int s = 0;
#pragma unroll
    for (int j = 0; j < 8; j++) { pre[j] = s; s += v[j]; }
    sm[tid] = s;
    __syncthreads();
#pragma unroll
    for (int off = 1; off < 1024; off <<= 1) {
        int t = (tid >= off) ? sm[tid - off] : 0;
        __syncthreads();
        sm[tid] += t;
        __syncthreads();
    }
    const int base = sm[tid] - s;  // exclusive
#pragma unroll
    for (int j = 0; j < 8; j++) {
        const int o = base + pre[j];
        g_off[tid * 8 + j] = o;
        g_cur[tid * 8 + j] = o;
    }
}

// ---------------------------------------------------------------------------
// Place: counting-sort tokens by segment into g_ord.
// ---------------------------------------------------------------------------
__global__ void place_kernel(const int* __restrict__ index) {
    const int t = blockIdx.x * blockDim.x + threadIdx.x;  // grid exact: TOT
    const int seg = (t / Nq) * IDXq + index[t];
    const int pos = atomicAdd(&g_cur[seg], 1);
    g_ord[pos] = t;
}

// ---------------------------------------------------------------------------
// Gather: one warp per segment. out[seg] = sum_t w_t * x_t; attn[t] = w_t.
// Single write per out row; zero atomic traffic.
// ---------------------------------------------------------------------------
__global__ void __launch_bounds__(256) gather_kernel(
    const float* __restrict__ x, float* __restrict__ out, float* __restrict__ attn)
{
    const int seg  = (blockIdx.x * blockDim.x + threadIdx.x) >> 5; // grid exact: SEGS warps
    const int lane = threadIdx.x & 31;
    const int start = g_off[seg];
    const int end   = g_cur[seg];   // after place: start + count
    const float ssum = g_segsum[seg];
    const float inv = (ssum > 0.0f) ? (1.0f / ssum) : 0.0f;

    float4 acc = make_float4(0.f, 0.f, 0.f, 0.f);
    int i = start;
    for (; i + 4 <= end; i += 4) {
        const int t0 = g_ord[i],     t1 = g_ord[i + 1];
        const int t2 = g_ord[i + 2], t3 = g_ord[i + 3];
        const float w0 = g_e[t0] * inv, w1 = g_e[t1] * inv;
        const float w2 = g_e[t2] * inv, w3 = g_e[t3] * inv;
        const float4 v0 = reinterpret_cast<const float4*>(x + (size_t)t0 * Eq)[lane];
        const float4 v1 = reinterpret_cast<const float4*>(x + (size_t)t1 * Eq)[lane];
        const float4 v2 = reinterpret_cast<const float4*>(x + (size_t)t2 * Eq)[lane];
        const float4 v3 = reinterpret_cast<const float4*>(x + (size_t)t3 * Eq)[lane];
        acc.x = fmaf(w0, v0.x, acc.x); acc.y = fmaf(w0, v0.y, acc.y);
        acc.z = fmaf(w0, v0.z, acc.z); acc.w = fmaf(w0, v0.w, acc.w);
        acc.x = fmaf(w1, v1.x, acc.x); acc.y = fmaf(w1, v1.y, acc.y);
        acc.z = fmaf(w1, v1.z, acc.z); acc.w = fmaf(w1, v1.w, acc.w);
        acc.x = fmaf(w2, v2.x, acc.x); acc.y = fmaf(w2, v2.y, acc.y);
        acc.z = fmaf(w2, v2.z, acc.z); acc.w = fmaf(w2, v2.w, acc.w);
        acc.x = fmaf(w3, v3.x, acc.x); acc.y = fmaf(w3, v3.y, acc.y);
        acc.z = fmaf(w3, v3.z, acc.z); acc.w = fmaf(w3, v3.w, acc.w);
        if (lane == 0) { attn[t0] = w0; attn[t1] = w1; attn[t2] = w2; attn[t3] = w3; }
    }
    for (; i < end; i++) {
        const int t = g_ord[i];
        const float w = g_e[t] * inv;
        const float4 v = reinterpret_cast<const float4*>(x + (size_t)t * Eq)[lane];
        acc.x = fmaf(w, v.x, acc.x); acc.y = fmaf(w, v.y, acc.y);
        acc.z = fmaf(w, v.z, acc.z); acc.w = fmaf(w, v.w, acc.w);
        if (lane == 0) attn[t] = w;
    }
    reinterpret_cast<float4*>(out + (size_t)seg * Eq)[lane] = acc;
}

// ---------------------------------------------------------------------------
extern "C" void kernel_launch(void* const* d_in, const int* in_sizes, int n_in,
                              void* d_out, int out_size)
{
    const float* x     = (const float*)d_in[0];
    const float* W     = (const float*)d_in[1];
    const float* bias  = (const float*)d_in[2];
    const float* ctx   = (const float*)d_in[3];
    const int*   mask  = (const int*)d_in[4];
    const int*   index = (const int*)d_in[5];

    float* out  = (float*)d_out;        // [B, IDX, E]
    float* attn = out + OUTF;           // [B, N]

    cudaFuncSetAttribute(score_kernel, cudaFuncAttributeMaxDynamicSharedMemorySize, SM_TOTAL);

    wprep_kernel<<<Eq * Eq / 256, 256>>>(W);
    zinit_kernel<<<SEGS / 256, 256>>>();
    score_kernel<<<152, 256, SM_TOTAL>>>(x, bias, ctx, mask, index);
    scan_kernel<<<1, 1024>>>();
    place_kernel<<<TOT / 256, 256>>>(index);
    gather_kernel<<<SEGS / 8, 256>>>(x, out, attn);
}

// round 10
// speedup vs baseline: 1.0615x; 1.0615x over previous
#include <cuda_runtime.h>
#include <cuda_bf16.h>
#include <math.h>
#include <stdint.h>

#define Bq   4
#define Nq   200000
#define Eq   128
#define IDXq 2048
#define TOT  (Bq * Nq)        // 800000 tokens
#define SEGS (Bq * IDXq)      // 8192 segments
#define OUTF (SEGS * Eq)      // 1048576 floats in `out` region
#define TM   128              // tokens per tile
#define TILES (TOT / TM)      // 6250 tiles
#define ROWB 272              // padded bf16 smem row stride (128 bf16 + 8 pad)
#define RAWS 528              // padded fp32 raw row stride bytes (132 floats)

// ---------------- device scratch (no cudaMalloc allowed) -------------------
__device__ float g_e[TOT];
__device__ float g_segsum[SEGS];
__device__ __nv_bfloat16 g_Whi[Eq * Eq];
__device__ __nv_bfloat16 g_Wlo[Eq * Eq];

// ---------------- helpers ---------------------------------------------------
__device__ __forceinline__ uint32_t smem_u32(const void* p) {
    uint32_t a;
    asm("{ .reg .u64 t; cvta.to.shared.u64 t, %1; cvt.u32.u64 %0, t; }" : "=r"(a) : "l"(p));
    return a;
}
__device__ __forceinline__ uint32_t pack_bf16x2(float a, float b) {  // lo=a, hi=b
    uint32_t r;
    asm("cvt.rn.bf16x2.f32 %0, %1, %2;" : "=r"(r) : "f"(b), "f"(a));
    return r;
}
__device__ __forceinline__ float2 unpack_bf16x2(uint32_t u) {
    __nv_bfloat162 h = *reinterpret_cast<__nv_bfloat162*>(&u);
    return __bfloat1622float2(h);
}
__device__ __forceinline__ void cp_async16(uint32_t saddr, const void* gaddr) {
    asm volatile("cp.async.cg.shared.global [%0], [%1], 16;" :: "r"(saddr), "l"(gaddr));
}
__device__ __forceinline__ void ldsm_x4(uint32_t addr, uint32_t& r0, uint32_t& r1,
                                        uint32_t& r2, uint32_t& r3) {
    asm volatile("ldmatrix.sync.aligned.m8n8.x4.shared.b16 {%0,%1,%2,%3}, [%4];"
                 : "=r"(r0), "=r"(r1), "=r"(r2), "=r"(r3) : "r"(addr));
}
__device__ __forceinline__ void mma_bf16(float* d, uint32_t a0, uint32_t a1, uint32_t a2,
                                         uint32_t a3, uint32_t b0, uint32_t b1) {
    asm volatile(
        "mma.sync.aligned.m16n8k16.row.col.f32.bf16.bf16.f32 "
        "{%0,%1,%2,%3}, {%4,%5,%6,%7}, {%8,%9}, {%0,%1,%2,%3};"
        : "+f"(d[0]), "+f"(d[1]), "+f"(d[2]), "+f"(d[3])
        : "r"(a0), "r"(a1), "r"(a2), "r"(a3), "r"(b0), "r"(b1));
}
// tanh(x) = 1 - 2/(exp(2x)+1), via ex2.approx + rcp.approx (~2^-21 max rel err)
__device__ __forceinline__ float fast_tanh(float x) {
    float e, r;
    asm("ex2.approx.f32 %0, %1;" : "=f"(e) : "f"(x * 2.8853900817779268f));
    asm("rcp.approx.f32 %0, %1;" : "=f"(r) : "f"(e + 1.0f));
    return fmaf(-2.0f, r, 1.0f);
}
__device__ __forceinline__ void red_add_v4(float* dst, float a, float b, float c, float d) {
    asm volatile("red.global.add.v4.f32 [%0], {%1, %2, %3, %4};"
                 :: "l"(dst), "f"(a), "f"(b), "f"(c), "f"(d) : "memory");
}

// ---------------------------------------------------------------------------
__global__ void wprep_kernel(const float* __restrict__ W) {
    int i = blockIdx.x * blockDim.x + threadIdx.x; // 16384 exact
    float w = W[i];
    __nv_bfloat16 hi = __float2bfloat16_rn(w);
    g_Whi[i] = hi;
    g_Wlo[i] = __float2bfloat16_rn(w - __bfloat162float(hi));
}

// zero out region + segsum (idempotent across graph replays)
__global__ void init_kernel(float* __restrict__ out) {
    int i = blockIdx.x * blockDim.x + threadIdx.x;   // grid exact: OUTF/4
    reinterpret_cast<float4*>(out)[i] = make_float4(0.f, 0.f, 0.f, 0.f);
    if (i < SEGS) g_segsum[i] = 0.0f;
}

// ---------------------------------------------------------------------------
// Score + fused scatter: persistent HMMA bf16x3-split GEMM, cp.async pipelined.
// Per tile: z = x W^T, e = mask ? exp(ctx.tanh(z+b)/sqrt(E)) : 0  (no-max
// softmax: scores bounded, masked exp underflows to 0), then scatter
// RED out[seg] += e * (xh + xl)  directly from the smem-resident tile.
// ---------------------------------------------------------------------------
#define SM_B   0
#define SM_C   512
#define SM_P   1024                     // partial[128][2] floats
#define SM_E   2048                     // e per row [128]
#define SM_S   2560                     // seg per row [128] ints
#define SM_WH  3072
#define SM_WL  (SM_WH + 128 * ROWB)
#define SM_XH  (SM_WL + 128 * ROWB)
#define SM_XL  (SM_XH + 128 * ROWB)
#define SM_RAW (SM_XL + 128 * ROWB)     // fp32 raw tile, stride 528B
#define SM_TOTAL (SM_RAW + 128 * RAWS)  // 209920

__global__ void __launch_bounds__(256, 1) score_kernel(
    const float* __restrict__ x, const float* __restrict__ bias,
    const float* __restrict__ ctx, const int* __restrict__ mask,
    const int* __restrict__ index, float* __restrict__ out)
{
    extern __shared__ char smem[];
    const uint32_t sb = smem_u32(smem);
    const int tid  = threadIdx.x;
    const int wid  = tid >> 5;
    const int lane = tid & 31;

    float* bS = reinterpret_cast<float*>(smem + SM_B);
    float* cS = reinterpret_cast<float*>(smem + SM_C);
    float* pS = reinterpret_cast<float*>(smem + SM_P);
    float* eS = reinterpret_cast<float*>(smem + SM_E);
    int*   sS = reinterpret_cast<int*>(smem + SM_S);
    if (tid < 128) { bS[tid] = bias[tid]; cS[tid] = ctx[tid]; }

    // stage W hi/lo (row f, stride 272B). 256 thr, 128 rows.
    {
        const int r = tid >> 1;
        const int c0 = (tid & 1) * 64;
#pragma unroll
        for (int i = 0; i < 8; i++) {
            const int c = c0 + i * 8;
            *reinterpret_cast<uint4*>(smem + SM_WH + r * ROWB + c * 2) =
                *reinterpret_cast<const uint4*>(&g_Whi[r * Eq + c]);
            *reinterpret_cast<uint4*>(smem + SM_WL + r * ROWB + c * 2) =
                *reinterpret_cast<const uint4*>(&g_Wlo[r * Eq + c]);
        }
    }

    const int xr   = tid >> 1;
    const int half = (tid & 1) * 64;
    const uint32_t rawBase = sb + SM_RAW + (uint32_t)xr * RAWS + (uint32_t)half * 4;

    const int rowG = (wid >> 1) * 32;
    const int colG = (wid & 1) * 64;

    const uint32_t aColB = (lane >> 4) * 16;
    const uint32_t aAddr0H = sb + SM_XH + (uint32_t)(rowG + (lane & 15)) * ROWB + aColB;
    const uint32_t aAddr1H = aAddr0H + 16 * ROWB;
    const uint32_t dXL = (uint32_t)(SM_XL - SM_XH);
    const int rowB = (lane & 7) + ((lane & 16) >> 1);
    const uint32_t colB = (lane & 8) ? 16u : 0u;
    const uint32_t bBaseH = sb + SM_WH + (uint32_t)(colG + rowB) * ROWB + colB;
    const uint32_t dWL = (uint32_t)(SM_WL - SM_WH);

    // ---- prologue: cp.async tile0 -> raw, convert to hi/lo ----
    int tile = blockIdx.x;
    {
        const float* xrow = x + (size_t)(tile * TM + xr) * Eq + half;
#pragma unroll
        for (int i = 0; i < 16; i++) cp_async16(rawBase + i * 16, xrow + i * 4);
        asm volatile("cp.async.commit_group;" ::: "memory");
        asm volatile("cp.async.wait_group 0;" ::: "memory");
    }
    __syncthreads();
#pragma unroll
    for (int i = 0; i < 8; i++) {
        float4 f0 = *reinterpret_cast<const float4*>(smem + (rawBase - sb) + i * 32);
        float4 f1 = *reinterpret_cast<const float4*>(smem + (rawBase - sb) + i * 32 + 16);
        float fv[8] = {f0.x, f0.y, f0.z, f0.w, f1.x, f1.y, f1.z, f1.w};
        float hv[8], lv[8];
#pragma unroll
        for (int j = 0; j < 8; j++) {
            hv[j] = __bfloat162float(__float2bfloat16_rn(fv[j]));
            lv[j] = fv[j] - hv[j];
        }
        uint4 uh, ul;
        uh.x = pack_bf16x2(hv[0], hv[1]); uh.y = pack_bf16x2(hv[2], hv[3]);
        uh.z = pack_bf16x2(hv[4], hv[5]); uh.w = pack_bf16x2(hv[6], hv[7]);
        ul.x = pack_bf16x2(lv[0], lv[1]); ul.y = pack_bf16x2(lv[2], lv[3]);
        ul.z = pack_bf16x2(lv[4], lv[5]); ul.w = pack_bf16x2(lv[6], lv[7]);
        const int c = half + i * 8;
        *reinterpret_cast<uint4*>(smem + SM_XH + xr * ROWB + c * 2) = uh;
        *reinterpret_cast<uint4*>(smem + SM_XL + xr * ROWB + c * 2) = ul;
    }
    __syncthreads();

    while (tile < TILES) {
        const int tbase = tile * TM;
        const int next  = tile + gridDim.x;

        // ---- issue cp.async for next tile ----
        if (next < TILES) {
            const float* xrow = x + (size_t)(next * TM + xr) * Eq + half;
#pragma unroll
            for (int i = 0; i < 16; i++) cp_async16(rawBase + i * 16, xrow + i * 4);
            asm volatile("cp.async.commit_group;" ::: "memory");
        }

        // ---- MMA mainloop: d = xh*Wh + xh*Wl + xl*Wh ----
        float d[2][8][4];
#pragma unroll
        for (int mb = 0; mb < 2; mb++)
#pragma unroll
            for (int nb = 0; nb < 8; nb++)
#pragma unroll
                for (int j = 0; j < 4; j++) d[mb][nb][j] = 0.0f;

#pragma unroll
        for (int k = 0; k < 8; k++) {
            const uint32_t ko = (uint32_t)k * 32;
            uint32_t ah[2][4], al[2][4];
            ldsm_x4(aAddr0H + ko,       ah[0][0], ah[0][1], ah[0][2], ah[0][3]);
            ldsm_x4(aAddr0H + dXL + ko, al[0][0], al[0][1], al[0][2], al[0][3]);
            ldsm_x4(aAddr1H + ko,       ah[1][0], ah[1][1], ah[1][2], ah[1][3]);
            ldsm_x4(aAddr1H + dXL + ko, al[1][0], al[1][1], al[1][2], al[1][3]);
#pragma unroll
            for (int nb = 0; nb < 4; nb++) {
                uint32_t bh0, bh1, bh2, bh3, bl0, bl1, bl2, bl3;
                const uint32_t boff = (uint32_t)nb * (16 * ROWB) + ko;
                ldsm_x4(bBaseH + boff,       bh0, bh1, bh2, bh3);
                ldsm_x4(bBaseH + dWL + boff, bl0, bl1, bl2, bl3);
#pragma unroll
                for (int mb = 0; mb < 2; mb++) {
                    mma_bf16(d[mb][nb * 2],     ah[mb][0], ah[mb][1], ah[mb][2], ah[mb][3], bh0, bh1);
                    mma_bf16(d[mb][nb * 2],     ah[mb][0], ah[mb][1], ah[mb][2], ah[mb][3], bl0, bl1);
                    mma_bf16(d[mb][nb * 2],     al[mb][0], al[mb][1], al[mb][2], al[mb][3], bh0, bh1);
                    mma_bf16(d[mb][nb * 2 + 1], ah[mb][0], ah[mb][1], ah[mb][2], ah[mb][3], bh2, bh3);
                    mma_bf16(d[mb][nb * 2 + 1], ah[mb][0], ah[mb][1], ah[mb][2], ah[mb][3], bl2, bl3);
                    mma_bf16(d[mb][nb * 2 + 1], al[mb][0], al[mb][1], al[mb][2], al[mb][3], bh2, bh3);
                }
            }
        }

        // ---- epilogue: per-warp partial of ctx . tanh(z + b) over 64 cols ----
#pragma unroll
        for (int mb = 0; mb < 2; mb++) {
            float p0 = 0.0f, p1 = 0.0f;
#pragma unroll
            for (int nb = 0; nb < 8; nb++) {
                const int n0 = colG + nb * 8 + (lane & 3) * 2;
                const float2 bb = *reinterpret_cast<const float2*>(&bS[n0]);
                const float2 cc = *reinterpret_cast<const float2*>(&cS[n0]);
                p0 = fmaf(fast_tanh(d[mb][nb][0] + bb.x), cc.x, p0);
                p0 = fmaf(fast_tanh(d[mb][nb][1] + bb.y), cc.y, p0);
                p1 = fmaf(fast_tanh(d[mb][nb][2] + bb.x), cc.x, p1);
                p1 = fmaf(fast_tanh(d[mb][nb][3] + bb.y), cc.y, p1);
            }
            p0 += __shfl_xor_sync(0xffffffffu, p0, 1);
            p0 += __shfl_xor_sync(0xffffffffu, p0, 2);
            p1 += __shfl_xor_sync(0xffffffffu, p1, 1);
            p1 += __shfl_xor_sync(0xffffffffu, p1, 2);
            if ((lane & 3) == 0) {
                const int r = rowG + mb * 16 + (lane >> 2);
                pS[r * 2 + (wid & 1)]       = p0;
                pS[(r + 8) * 2 + (wid & 1)] = p1;
            }
        }
        asm volatile("cp.async.wait_group 0;" ::: "memory");
        __syncthreads();   // partials visible; ldsm done; raw tile landed

        // ---- finalize: e = mask ? exp(score) : 0; segsum += e ----
        if (tid < 128) {
            const int tok = tbase + tid;
            const float s = (pS[tid * 2] + pS[tid * 2 + 1]) * 0.08838834764831845f;
            const float e = (mask[tok] == 0) ? 0.0f : __expf(s);
            g_e[tok] = e;
            const int seg = (tok / Nq) * IDXq + index[tok];
            eS[tid] = e;
            sS[tid] = seg;
            atomicAdd(&g_segsum[seg], e);
        }
        __syncthreads();   // eS/sS visible to all 256 threads

        // ---- fused scatter: out[seg] += e * (xh + xl), from own smem rows ----
        {
            const float ev = eS[xr];
            if (ev != 0.0f) {
                float* orow = out + (size_t)sS[xr] * Eq + half;
#pragma unroll
                for (int i = 0; i < 8; i++) {
                    const int c = half + i * 8;
                    const uint4 uh = *reinterpret_cast<const uint4*>(smem + SM_XH + xr * ROWB + c * 2);
                    const uint4 ul = *reinterpret_cast<const uint4*>(smem + SM_XL + xr * ROWB + c * 2);
                    const float2 h0 = unpack_bf16x2(uh.x), l0 = unpack_bf16x2(ul.x);
                    const float2 h1 = unpack_bf16x2(uh.y), l1 = unpack_bf16x2(ul.y);
                    const float2 h2 = unpack_bf16x2(uh.z), l2 = unpack_bf16x2(ul.z);
                    const float2 h3 = unpack_bf16x2(uh.w), l3 = unpack_bf16x2(ul.w);
                    red_add_v4(orow + i * 8,
                               ev * (h0.x + l0.x), ev * (h0.y + l0.y),
                               ev * (h1.x + l1.x), ev * (h1.y + l1.y));
                    red_add_v4(orow + i * 8 + 4,
                               ev * (h2.x + l2.x), ev * (h2.y + l2.y),
                               ev * (h3.x + l3.x), ev * (h3.y + l3.y));
                }
            }
        }

        // ---- convert raw -> hi/lo for next tile (own rows; scatter done) ----
        if (next < TILES) {
#pragma unroll
            for (int i = 0; i < 8; i++) {
                float4 f0 = *reinterpret_cast<const float4*>(smem + (rawBase - sb) + i * 32);
                float4 f1 = *reinterpret_cast<const float4*>(smem + (rawBase - sb) + i * 32 + 16);
                float fv[8] = {f0.x, f0.y, f0.z, f0.w, f1.x, f1.y, f1.z, f1.w};
                float hv[8], lv[8];
#pragma unroll
                for (int j = 0; j < 8; j++) {
                    hv[j] = __bfloat162float(__float2bfloat16_rn(fv[j]));
                    lv[j] = fv[j] - hv[j];
                }
                uint4 uh, ul;
                uh.x = pack_bf16x2(hv[0], hv[1]); uh.y = pack_bf16x2(hv[2], hv[3]);
                uh.z = pack_bf16x2(hv[4], hv[5]); uh.w = pack_bf16x2(hv[6], hv[7]);
                ul.x = pack_bf16x2(lv[0], lv[1]); ul.y = pack_bf16x2(lv[2], lv[3]);
                ul.z = pack_bf16x2(lv[4], lv[5]); ul.w = pack_bf16x2(lv[6], lv[7]);
                const int c = half + i * 8;
                *reinterpret_cast<uint4*>(smem + SM_XH + xr * ROWB + c * 2) = uh;
                *reinterpret_cast<uint4*>(smem + SM_XL + xr * ROWB + c * 2) = ul;
            }
        }
        __syncthreads();
        tile = next;
    }
}

// ---------------------------------------------------------------------------
// attn[t] = e[t] / segsum[seg(t)]  (masked tokens: e=0 -> w=0)
// ---------------------------------------------------------------------------
__global__ void attn_kernel(const int* __restrict__ index, float* __restrict__ attn) {
    const int t0 = (blockIdx.x * blockDim.x + threadIdx.x) * 4;  // grid exact: TOT/4
    const int b = t0 / Nq;
    const int4 idx = *reinterpret_cast<const int4*>(&index[t0]);
    const float4 e = *reinterpret_cast<const float4*>(&g_e[t0]);
    const float s0 = g_segsum[b * IDXq + idx.x];
    const float s1 = g_segsum[b * IDXq + idx.y];
    const float s2 = g_segsum[b * IDXq + idx.z];
    const float s3 = g_segsum[b * IDXq + idx.w];
    float4 w;
    w.x = (s0 > 0.0f) ? e.x / s0 : 0.0f;
    w.y = (s1 > 0.0f) ? e.y / s1 : 0.0f;
    w.z = (s2 > 0.0f) ? e.z / s2 : 0.0f;
    w.w = (s3 > 0.0f) ? e.w / s3 : 0.0f;
    *reinterpret_cast<float4*>(&attn[t0]) = w;
}

// ---------------------------------------------------------------------------
// out[seg] /= segsum[seg]
// ---------------------------------------------------------------------------
__global__ void outdiv_kernel(float* __restrict__ out) {
    const int i = blockIdx.x * blockDim.x + threadIdx.x;  // grid exact: OUTF/4
    const int seg = i >> 5;                               // 32 float4 per row
    const float ssum = g_segsum[seg];
    const float inv = (ssum > 0.0f) ? (1.0f / ssum) : 0.0f;
    float4 v = reinterpret_cast<const float4*>(out)[i];
    v.x *= inv; v.y *= inv; v.z *= inv; v.w *= inv;
    reinterpret_cast<float4*>(out)[i] = v;
}

// ---------------------------------------------------------------------------
extern "C" void kernel_launch(void* const* d_in, const int* in_sizes, int n_in,
                              void* d_out, int out_size)
{
    const float* x     = (const float*)d_in[0];
    const float* W     = (const float*)d_in[1];
    const float* bias  = (const float*)d_in[2];
    const float* ctx   = (const float*)d_in[3];
    const int*   mask  = (const int*)d_in[4];
    const int*   index = (const int*)d_in[5];

    float* out  = (float*)d_out;        // [B, IDX, E]
    float* attn = out + OUTF;           // [B, N]

    cudaFuncSetAttribute(score_kernel, cudaFuncAttributeMaxDynamicSharedMemorySize, SM_TOTAL);

    wprep_kernel<<<Eq * Eq / 256, 256>>>(W);
    init_kernel<<<OUTF / 4 / 256, 256>>>(out);
    score_kernel<<<152, 256, SM_TOTAL>>>(x, bias, ctx, mask, index, out);
    attn_kernel<<<TOT / 4 / 320, 320>>>(index, attn);
    outdiv_kernel<<<OUTF / 4 / 256, 256>>>(out);
}